// round 1
// baseline (speedup 1.0000x reference)
#include <cuda_runtime.h>
#include <math.h>

// ----------------------------------------------------------------------------
// Software rasterizer matching the JAX reference:
//   winner(pixel) = argmax over covering triangles of (z, index) lexicographic,
//   with zbuf initialized to min vertex z. Deferred shading: one bilinear
//   texture sample per pixel at the end.
// Triangles are pre-sorted by zmax descending so each pixel can terminate the
// scan as soon as zmax < best_z (no remaining triangle can win).
// ----------------------------------------------------------------------------

#define MAXK  2048
#define CHUNK 256

__device__ float4 g_tri[MAXK * 4];   // sorted triangle structs
__device__ float  g_key[MAXK];       // sort keys (-zmax, +INF for inactive/pad)
__device__ int    g_order[MAXK];     // sorted order (triangle ids)
__device__ float  g_zinit;           // min vertex z

// ---- min vertex z ----------------------------------------------------------
__global__ void zinit_kernel(const float* __restrict__ vertices, int V) {
    __shared__ float red[256];
    float m = INFINITY;
    for (int v = threadIdx.x; v < V; v += 256)
        m = fminf(m, vertices[v * 3 + 2]);
    red[threadIdx.x] = m;
    __syncthreads();
    for (int s = 128; s > 0; s >>= 1) {
        if (threadIdx.x < s)
            red[threadIdx.x] = fminf(red[threadIdx.x], red[threadIdx.x + s]);
        __syncthreads();
    }
    if (threadIdx.x == 0) g_zinit = red[0];
}

// ---- per-triangle sort key: -zmax (active) or +INF (inactive / padding) ----
__global__ void key_kernel(const float* __restrict__ vertices,
                           const int* __restrict__ faces, int K) {
    int t = blockIdx.x * blockDim.x + threadIdx.x;
    if (t >= MAXK) return;
    float key = INFINITY;
    if (t < K) {
        int i0 = faces[t*3+0], i1 = faces[t*3+1], i2 = faces[t*3+2];
        float v0x = vertices[i0*3+0], v0y = vertices[i0*3+1], v0z = vertices[i0*3+2];
        float v1x = vertices[i1*3+0], v1y = vertices[i1*3+1], v1z = vertices[i1*3+2];
        float v2x = vertices[i2*3+0], v2y = vertices[i2*3+1], v2z = vertices[i2*3+2];
        float w = (v1x - v0x) * (v2y - v0y) - (v1y - v0y) * (v2x - v0x);
        if (w >= 1e-9f)
            key = -fmaxf(v0z, fmaxf(v1z, v2z));
    }
    g_key[t] = key;
}

// ---- one-block bitonic sort (ascending by key) -----------------------------
__global__ void sort_kernel() {
    __shared__ float sk[MAXK];
    __shared__ int   sv[MAXK];
    int tid = threadIdx.x;
    int nth = blockDim.x;
    for (int i = tid; i < MAXK; i += nth) { sk[i] = g_key[i]; sv[i] = i; }
    __syncthreads();
    for (int k = 2; k <= MAXK; k <<= 1) {
        for (int j = k >> 1; j > 0; j >>= 1) {
            for (int i = tid; i < MAXK; i += nth) {
                int ixj = i ^ j;
                if (ixj > i) {
                    bool up = ((i & k) == 0);
                    float ka = sk[i], kb = sk[ixj];
                    if (up ? (ka > kb) : (ka < kb)) {
                        sk[i] = kb; sk[ixj] = ka;
                        int va = sv[i]; sv[i] = sv[ixj]; sv[ixj] = va;
                    }
                }
            }
            __syncthreads();
        }
    }
    for (int i = tid; i < MAXK; i += nth) g_order[i] = sv[i];
}

// ---- build sorted triangle structs -----------------------------------------
// Layout per triangle (4 x float4):
//  [0] A0 B0 C0 zmax   (edge pAB: A*px + B*py + C)
//  [1] A1 B1 C1 z0     (edge pCB -> w1, pairs with vertex0 z)
//  [2] A2 B2 C2 z1     (edge pCA -> w2, pairs with vertex1 z)
//  [3] w   z2  idx  0
__global__ void build_kernel(const float* __restrict__ vertices,
                             const int* __restrict__ faces, int K) {
    int s = blockIdx.x * blockDim.x + threadIdx.x;
    if (s >= K) return;
    int t = g_order[s];
    float4 f0, f1, f2, f3;
    bool ok = false;
    if (t < K) {
        int i0 = faces[t*3+0], i1 = faces[t*3+1], i2 = faces[t*3+2];
        float v0x = vertices[i0*3+0], v0y = vertices[i0*3+1], v0z = vertices[i0*3+2];
        float v1x = vertices[i1*3+0], v1y = vertices[i1*3+1], v1z = vertices[i1*3+2];
        float v2x = vertices[i2*3+0], v2y = vertices[i2*3+1], v2z = vertices[i2*3+2];
        float w = (v1x - v0x) * (v2y - v0y) - (v1y - v0y) * (v2x - v0x);
        if (w >= 1e-9f) {
            ok = true;
            // pAB = (px - v1x)*(v0y - v1y) - (py - v1y)*(v0x - v1x)
            float a0 = v0y - v1y, b0 = v0x - v1x;
            float C0 = (float)((double)v1y * (double)b0 - (double)v1x * (double)a0);
            // pCB = (px - v2x)*(v1y - v2y) - (py - v2y)*(v1x - v2x)
            float a1 = v1y - v2y, b1 = v1x - v2x;
            float C1 = (float)((double)v2y * (double)b1 - (double)v2x * (double)a1);
            // pCA = (px - v0x)*(v2y - v0y) - (py - v0y)*(v2x - v0x)
            float a2 = v2y - v0y, b2 = v2x - v0x;
            float C2 = (float)((double)v0y * (double)b2 - (double)v0x * (double)a2);
            float zmax = fmaxf(v0z, fmaxf(v1z, v2z));
            f0 = make_float4(a0, -b0, C0, zmax);
            f1 = make_float4(a1, -b1, C1, v0z);
            f2 = make_float4(a2, -b2, C2, v1z);
            f3 = make_float4(w, v2z, __int_as_float(t), 0.0f);
        }
    }
    if (!ok) {
        float ninf = __int_as_float(0xff800000);  // -inf: always terminates scan
        f0 = make_float4(0.f, 0.f, 0.f, ninf);
        f1 = make_float4(0.f, 0.f, 0.f, 0.f);
        f2 = make_float4(0.f, 0.f, 0.f, 0.f);
        f3 = make_float4(1.f, 0.f, __int_as_float(-1), 0.f);
    }
    g_tri[s*4+0] = f0; g_tri[s*4+1] = f1; g_tri[s*4+2] = f2; g_tri[s*4+3] = f3;
}

// ---- main render -----------------------------------------------------------
__global__ void __launch_bounds__(256) render_kernel(
    const int* __restrict__ uvfaces, const float* __restrict__ uv,
    const float* __restrict__ uvmap, float* __restrict__ out,
    int K, int S, int T)
{
    __shared__ float4 s_tri[CHUNK * 4];

    int j = blockIdx.x * 32 + threadIdx.x;
    int i = blockIdx.y * 8 + threadIdx.y;
    int tid = threadIdx.y * 32 + threadIdx.x;
    bool inrange = (j < S) && (i < S);
    int jc = min(j, S - 1), ic = min(i, S - 1);

    // pts[i][j] = (lin[j], lin[S-1-i]), lin = linspace(-1, 1, S)
    float step = 2.0f / (float)(S - 1);
    float px = fmaf((float)jc, step, -1.0f);
    float py = fmaf((float)(S - 1 - ic), step, -1.0f);

    float bestz = g_zinit;   // zbuf init = min vertex z
    int   bestk = -1;
    float bw1 = 0.f, bw2 = 0.f;
    bool done = false;

    for (int base = 0; base < K; base += CHUNK) {
        int cnt = min(CHUNK, K - base);
        __syncthreads();
        for (int idx = tid; idx < cnt * 4; idx += 256)
            s_tri[idx] = g_tri[base * 4 + idx];
        __syncthreads();

        if (!done) {
            for (int t = 0; t < cnt; ++t) {
                float4 a = s_tri[t*4+0];
                if (a.w < bestz) { done = true; break; }  // sorted: nothing later can win
                float e0 = fmaf(a.x, px, fmaf(a.y, py, a.z));
                float4 b = s_tri[t*4+1];
                float e1 = fmaf(b.x, px, fmaf(b.y, py, b.z));
                float4 c = s_tri[t*4+2];
                float e2 = fmaf(c.x, px, fmaf(c.y, py, c.z));
                if (e0 > 0.f && e1 > 0.f && e2 > 0.f) {
                    float4 d = s_tri[t*4+3];
                    float w1 = e1 / d.x;          // pCB / w  (exact division like ref)
                    float w2 = e2 / d.x;          // pCA / w
                    float w3 = 1.0f - w1 - w2;
                    float z = w1 * b.w + w2 * c.w + w3 * d.y;
                    int k = __float_as_int(d.z);
                    if (z > bestz || (z == bestz && k > bestk)) {
                        bestz = z; bestk = k; bw1 = w1; bw2 = w2;
                    }
                }
            }
        }
        if (__syncthreads_and((int)done)) break;
    }

    if (!inrange) return;
    int SS = S * S;
    int p = i * S + j;

    if (bestk >= 0) {
        // deferred shading: fetch winner's uv triangle, interpolate, bilinear sample
        int f0 = uvfaces[bestk*3+0], f1 = uvfaces[bestk*3+1], f2i = uvfaces[bestk*3+2];
        float u0x = uv[f0*2+0]  * 2.0f - 1.0f, u0y = uv[f0*2+1]  * 2.0f - 1.0f;
        float u1x = uv[f1*2+0]  * 2.0f - 1.0f, u1y = uv[f1*2+1]  * 2.0f - 1.0f;
        float u2x = uv[f2i*2+0] * 2.0f - 1.0f, u2y = uv[f2i*2+1] * 2.0f - 1.0f;
        float w3 = 1.0f - bw1 - bw2;
        float x = bw1 * u0x + bw2 * u1x + w3 * u2x;
        float y = bw1 * u0y + bw2 * u1y + w3 * u2y;

        float ix = (x + 1.0f) * (float)(T - 1) * 0.5f;
        float iy = (y + 1.0f) * (float)(T - 1) * 0.5f;
        float ix0f = floorf(ix), iy0f = floorf(iy);
        float wx1 = ix - ix0f, wx0 = 1.0f - wx1;
        float wy1 = iy - iy0f, wy0 = 1.0f - wy1;
        int ix0 = (int)ix0f, iy0 = (int)iy0f;
        int ix1 = ix0 + 1,   iy1 = iy0 + 1;

        float m00 = (ix0 >= 0 && ix0 <= T-1 && iy0 >= 0 && iy0 <= T-1) ? 1.f : 0.f;
        float m01 = (ix1 >= 0 && ix1 <= T-1 && iy0 >= 0 && iy0 <= T-1) ? 1.f : 0.f;
        float m10 = (ix0 >= 0 && ix0 <= T-1 && iy1 >= 0 && iy1 <= T-1) ? 1.f : 0.f;
        float m11 = (ix1 >= 0 && ix1 <= T-1 && iy1 >= 0 && iy1 <= T-1) ? 1.f : 0.f;
        int cx0 = min(max(ix0, 0), T-1), cx1 = min(max(ix1, 0), T-1);
        int cy0 = min(max(iy0, 0), T-1), cy1 = min(max(iy1, 0), T-1);
        float k00 = (wy0 * wx0) * m00, k01 = (wy0 * wx1) * m01;
        float k10 = (wy1 * wx0) * m10, k11 = (wy1 * wx1) * m11;

        #pragma unroll
        for (int ch = 0; ch < 3; ++ch) {
            const float* img = uvmap + ch * T * T;
            float v = img[cy0*T + cx0] * k00 + img[cy0*T + cx1] * k01
                    + img[cy1*T + cx0] * k10 + img[cy1*T + cx1] * k11;
            out[ch*SS + p] = v;
        }
        out[3*SS + p] = 1.0f;
    } else {
        out[0*SS + p] = 0.f; out[1*SS + p] = 0.f;
        out[2*SS + p] = 0.f; out[3*SS + p] = 0.f;
    }
}

// ---- launch ----------------------------------------------------------------
extern "C" void kernel_launch(void* const* d_in, const int* in_sizes, int n_in,
                              void* d_out, int out_size) {
    const float* vertices = (const float*)d_in[0];
    const int*   faces    = (const int*)d_in[1];
    const float* uv       = (const float*)d_in[2];
    const int*   uvfaces  = (const int*)d_in[3];
    const float* uvmap    = (const float*)d_in[4];

    int V = in_sizes[0] / 3;
    int K = in_sizes[1] / 3;
    int T = (int)(sqrt((double)(in_sizes[4] / 3)) + 0.5);
    int S = (int)(sqrt((double)(out_size / 4)) + 0.5);
    if (K > MAXK) K = MAXK;

    zinit_kernel<<<1, 256>>>(vertices, V);
    key_kernel<<<(MAXK + 255) / 256, 256>>>(vertices, faces, K);
    sort_kernel<<<1, 1024>>>();
    build_kernel<<<(K + 255) / 256, 256>>>(vertices, faces, K);

    dim3 blk(32, 8);
    dim3 grd((S + 31) / 32, (S + 7) / 8);
    render_kernel<<<grd, blk>>>(uvfaces, uv, uvmap, (float*)d_out, K, S, T);
}

// round 4
// speedup vs baseline: 1.3611x; 1.3611x over previous
#include <cuda_runtime.h>
#include <math.h>

// ----------------------------------------------------------------------------
// Software rasterizer matching the JAX reference.
// winner(pixel) = lexicographic argmax over covering triangles of (z, index),
// zbuf init = min vertex z. Deferred shading (one bilinear sample per pixel).
// Triangles are bucket-sorted by zmax (descending); per-slot termination key is
// the EXACT suffix max of zmax, so a pixel scan stops as soon as no remaining
// triangle can beat its current best.
// ----------------------------------------------------------------------------

#define MAXK  2048
#define CHUNK 256
#define NBUK  256

__device__ float4 g_tri[MAXK * 4];   // bucket-ordered triangle structs
__device__ int    g_pos[MAXK];       // original tri -> slot (-1 if culled)
__device__ float  g_term[MAXK];      // per-slot termination key (suffix max zmax)
__device__ int    g_ntri;            // number of active slots
__device__ float  g_zinit;           // min vertex z

// ---- fused setup: zinit + zmax + bucket counting sort + suffix max ---------
__global__ void __launch_bounds__(1024) setup_kernel(
    const float* __restrict__ vertices, const int* __restrict__ faces,
    int V, int K)
{
    __shared__ float s_zmax[MAXK];
    __shared__ float s_bufA[MAXK];
    __shared__ float s_bufB[MAXK];
    __shared__ int   s_hist[NBUK];
    __shared__ int   s_cnt[NBUK];
    __shared__ float s_red[1024];
    __shared__ float sh_zh, sh_zl;
    __shared__ int   sh_n;
    int tid = threadIdx.x;

    // 1. zinit = min vertex z
    float m = INFINITY;
    for (int v = tid; v < V; v += 1024) m = fminf(m, vertices[v * 3 + 2]);
    s_red[tid] = m; __syncthreads();
    for (int s = 512; s > 0; s >>= 1) {
        if (tid < s) s_red[tid] = fminf(s_red[tid], s_red[tid + s]);
        __syncthreads();
    }
    if (tid == 0) g_zinit = s_red[0];
    __syncthreads();

    // 2. per-triangle zmax (-inf if culled), track valid range
    float mymax = -INFINITY, mymin = INFINITY;
    for (int t = tid; t < K; t += 1024) {
        int i0 = faces[3*t], i1 = faces[3*t+1], i2 = faces[3*t+2];
        float v0x = vertices[i0*3+0], v0y = vertices[i0*3+1], v0z = vertices[i0*3+2];
        float v1x = vertices[i1*3+0], v1y = vertices[i1*3+1], v1z = vertices[i1*3+2];
        float v2x = vertices[i2*3+0], v2y = vertices[i2*3+1], v2z = vertices[i2*3+2];
        float w = (v1x - v0x) * (v2y - v0y) - (v1y - v0y) * (v2x - v0x);
        float zm = -INFINITY;
        if (w >= 1e-9f) {
            zm = fmaxf(v0z, fmaxf(v1z, v2z));
            mymax = fmaxf(mymax, zm);
            mymin = fminf(mymin, zm);
        }
        s_zmax[t] = zm;
    }
    s_red[tid] = mymax; __syncthreads();
    for (int s = 512; s > 0; s >>= 1) {
        if (tid < s) s_red[tid] = fmaxf(s_red[tid], s_red[tid + s]);
        __syncthreads();
    }
    if (tid == 0) sh_zh = s_red[0];
    __syncthreads();
    s_red[tid] = mymin; __syncthreads();
    for (int s = 512; s > 0; s >>= 1) {
        if (tid < s) s_red[tid] = fminf(s_red[tid], s_red[tid + s]);
        __syncthreads();
    }
    if (tid == 0) sh_zl = s_red[0];
    __syncthreads();

    float zh = sh_zh, zl = sh_zl;
    float wd = fmaxf((zh - zl) / (float)NBUK, 1e-30f);

    // 3. histogram (bucket 0 = highest zmax)
    if (tid < NBUK) s_hist[tid] = 0;
    __syncthreads();
    for (int t = tid; t < K; t += 1024) {
        float zm = s_zmax[t];
        if (zm != -INFINITY) {
            int b = (int)((zh - zm) / wd);
            b = min(max(b, 0), NBUK - 1);
            atomicAdd(&s_hist[b], 1);
        }
    }
    __syncthreads();

    // 4. inclusive scan -> exclusive starts
    int cval = (tid < NBUK) ? s_hist[tid] : 0;
    if (tid < NBUK) s_cnt[tid] = cval;
    __syncthreads();
    for (int off = 1; off < NBUK; off <<= 1) {
        int v = 0;
        if (tid < NBUK && tid >= off) v = s_cnt[tid - off];
        __syncthreads();
        if (tid < NBUK) s_cnt[tid] += v;
        __syncthreads();
    }
    if (tid == NBUK - 1) sh_n = s_cnt[tid];      // total valid
    __syncthreads();
    if (tid < NBUK) s_cnt[tid] -= cval;          // running scatter counters
    __syncthreads();

    // 5. scatter: slot assignment + per-slot zmax
    for (int t = tid; t < K; t += 1024) {
        float zm = s_zmax[t];
        int pos = -1;
        if (zm != -INFINITY) {
            int b = (int)((zh - zm) / wd);
            b = min(max(b, 0), NBUK - 1);
            pos = atomicAdd(&s_cnt[b], 1);
            s_bufA[pos] = zm;
        }
        g_pos[t] = pos;
    }
    int n = sh_n;
    if (tid == 0) g_ntri = n;
    for (int i2 = tid; i2 < MAXK; i2 += 1024)
        if (i2 >= n) s_bufA[i2] = -INFINITY;
    __syncthreads();

    // 6. exact suffix max over slots (ping-pong Hillis-Steele)
    float* src = s_bufA;
    float* dst = s_bufB;
    for (int off = 1; off < MAXK; off <<= 1) {
        for (int i2 = tid; i2 < MAXK; i2 += 1024) {
            float a = src[i2];
            float b2 = (i2 + off < MAXK) ? src[i2 + off] : -INFINITY;
            dst[i2] = fmaxf(a, b2);
        }
        __syncthreads();
        float* tmp = src; src = dst; dst = tmp;
    }
    for (int i2 = tid; i2 < n; i2 += 1024) g_term[i2] = src[i2];
}

// ---- build bucket-ordered triangle structs ---------------------------------
// Layout per slot (4 x float4):
//  [0] A0 B0 C0 term   (edge pAB: A*px + B*py + C; term = suffix-max zmax)
//  [1] A1 B1 C1 z0     (edge pCB -> w1)
//  [2] A2 B2 C2 z1     (edge pCA -> w2)
//  [3] w   z2  idx  0
__global__ void build_kernel(const float* __restrict__ vertices,
                             const int* __restrict__ faces, int K) {
    int t = blockIdx.x * blockDim.x + threadIdx.x;
    if (t >= K) return;
    int pos = g_pos[t];
    if (pos < 0) return;

    int i0 = faces[t*3+0], i1 = faces[t*3+1], i2 = faces[t*3+2];
    float v0x = vertices[i0*3+0], v0y = vertices[i0*3+1], v0z = vertices[i0*3+2];
    float v1x = vertices[i1*3+0], v1y = vertices[i1*3+1], v1z = vertices[i1*3+2];
    float v2x = vertices[i2*3+0], v2y = vertices[i2*3+1], v2z = vertices[i2*3+2];
    float w = (v1x - v0x) * (v2y - v0y) - (v1y - v0y) * (v2x - v0x);

    // pAB = (px - v1x)*(v0y - v1y) - (py - v1y)*(v0x - v1x)
    float a0 = v0y - v1y, b0 = v0x - v1x;
    float C0 = (float)((double)v1y * (double)b0 - (double)v1x * (double)a0);
    // pCB = (px - v2x)*(v1y - v2y) - (py - v2y)*(v1x - v2x)
    float a1 = v1y - v2y, b1 = v1x - v2x;
    float C1 = (float)((double)v2y * (double)b1 - (double)v2x * (double)a1);
    // pCA = (px - v0x)*(v2y - v0y) - (py - v0y)*(v2x - v0x)
    float a2 = v2y - v0y, b2 = v2x - v0x;
    float C2 = (float)((double)v0y * (double)b2 - (double)v0x * (double)a2);

    g_tri[pos*4+0] = make_float4(a0, -b0, C0, g_term[pos]);
    g_tri[pos*4+1] = make_float4(a1, -b1, C1, v0z);
    g_tri[pos*4+2] = make_float4(a2, -b2, C2, v1z);
    g_tri[pos*4+3] = make_float4(w, v2z, __int_as_float(t), 0.0f);
}

// ---- main render -----------------------------------------------------------
__global__ void __launch_bounds__(256) render_kernel(
    const int* __restrict__ uvfaces, const float* __restrict__ uv,
    const float* __restrict__ uvmap, float* __restrict__ out,
    int S, int T)
{
    __shared__ float4 s_tri[CHUNK * 4];

    int n = g_ntri;

    int j = blockIdx.x * 32 + threadIdx.x;
    int i = blockIdx.y * 8 + threadIdx.y;
    int tid = threadIdx.y * 32 + threadIdx.x;
    bool inrange = (j < S) && (i < S);
    int jc = min(j, S - 1), ic = min(i, S - 1);

    // pts[i][j] = (lin[j], lin[S-1-i]), lin = linspace(-1, 1, S)
    float step = 2.0f / (float)(S - 1);
    float px = fmaf((float)jc, step, -1.0f);
    float py = fmaf((float)(S - 1 - ic), step, -1.0f);

    float bestz = g_zinit;
    int   bestk = -1;
    float bw1 = 0.f, bw2 = 0.f;
    bool done = false;

    for (int base = 0; base < n; base += CHUNK) {
        int cnt = min(CHUNK, n - base);
        __syncthreads();
        for (int idx = tid; idx < cnt * 4; idx += 256)
            s_tri[idx] = g_tri[base * 4 + idx];
        __syncthreads();

        if (!done) {
            // term keys are non-increasing: if the chunk head can't beat
            // bestz, nothing in or after this chunk can.
            if (s_tri[0].w < bestz) {
                done = true;
            } else {
                for (int t = 0; t < cnt; ++t) {
                    float4 a = s_tri[t*4+0];
                    if (a.w < bestz) { done = true; break; }
                    float e0 = fmaf(a.x, px, fmaf(a.y, py, a.z));
                    float4 b = s_tri[t*4+1];
                    float e1 = fmaf(b.x, px, fmaf(b.y, py, b.z));
                    float4 c = s_tri[t*4+2];
                    float e2 = fmaf(c.x, px, fmaf(c.y, py, c.z));
                    if (fminf(e0, fminf(e1, e2)) > 0.f) {
                        float4 d = s_tri[t*4+3];
                        float w1 = e1 / d.x;          // pCB / w (exact like ref)
                        float w2 = e2 / d.x;          // pCA / w
                        float w3 = 1.0f - w1 - w2;
                        float z = w1 * b.w + w2 * c.w + w3 * d.y;
                        int k = __float_as_int(d.z);
                        if (z > bestz || (z == bestz && k > bestk)) {
                            bestz = z; bestk = k; bw1 = w1; bw2 = w2;
                        }
                    }
                }
            }
        }
        if (__syncthreads_and((int)done)) break;
    }

    if (!inrange) return;
    int SS = S * S;
    int p = i * S + j;

    if (bestk >= 0) {
        int f0 = uvfaces[bestk*3+0], f1 = uvfaces[bestk*3+1], f2i = uvfaces[bestk*3+2];
        float u0x = uv[f0*2+0]  * 2.0f - 1.0f, u0y = uv[f0*2+1]  * 2.0f - 1.0f;
        float u1x = uv[f1*2+0]  * 2.0f - 1.0f, u1y = uv[f1*2+1]  * 2.0f - 1.0f;
        float u2x = uv[f2i*2+0] * 2.0f - 1.0f, u2y = uv[f2i*2+1] * 2.0f - 1.0f;
        float w3 = 1.0f - bw1 - bw2;
        float x = bw1 * u0x + bw2 * u1x + w3 * u2x;
        float y = bw1 * u0y + bw2 * u1y + w3 * u2y;

        float ix = (x + 1.0f) * (float)(T - 1) * 0.5f;
        float iy = (y + 1.0f) * (float)(T - 1) * 0.5f;
        float ix0f = floorf(ix), iy0f = floorf(iy);
        float wx1 = ix - ix0f, wx0 = 1.0f - wx1;
        float wy1 = iy - iy0f, wy0 = 1.0f - wy1;
        int ix0 = (int)ix0f, iy0 = (int)iy0f;
        int ix1 = ix0 + 1,   iy1 = iy0 + 1;

        float m00 = (ix0 >= 0 && ix0 <= T-1 && iy0 >= 0 && iy0 <= T-1) ? 1.f : 0.f;
        float m01 = (ix1 >= 0 && ix1 <= T-1 && iy0 >= 0 && iy0 <= T-1) ? 1.f : 0.f;
        float m10 = (ix0 >= 0 && ix0 <= T-1 && iy1 >= 0 && iy1 <= T-1) ? 1.f : 0.f;
        float m11 = (ix1 >= 0 && ix1 <= T-1 && iy1 >= 0 && iy1 <= T-1) ? 1.f : 0.f;
        int cx0 = min(max(ix0, 0), T-1), cx1 = min(max(ix1, 0), T-1);
        int cy0 = min(max(iy0, 0), T-1), cy1 = min(max(iy1, 0), T-1);
        float k00 = (wy0 * wx0) * m00, k01 = (wy0 * wx1) * m01;
        float k10 = (wy1 * wx0) * m10, k11 = (wy1 * wx1) * m11;

        #pragma unroll
        for (int ch = 0; ch < 3; ++ch) {
            const float* img = uvmap + ch * T * T;
            float v = img[cy0*T + cx0] * k00 + img[cy0*T + cx1] * k01
                    + img[cy1*T + cx0] * k10 + img[cy1*T + cx1] * k11;
            out[ch*SS + p] = v;
        }
        out[3*SS + p] = 1.0f;
    } else {
        out[0*SS + p] = 0.f; out[1*SS + p] = 0.f;
        out[2*SS + p] = 0.f; out[3*SS + p] = 0.f;
    }
}

// ---- launch ----------------------------------------------------------------
extern "C" void kernel_launch(void* const* d_in, const int* in_sizes, int n_in,
                              void* d_out, int out_size) {
    const float* vertices = (const float*)d_in[0];
    const int*   faces    = (const int*)d_in[1];
    const float* uv       = (const float*)d_in[2];
    const int*   uvfaces  = (const int*)d_in[3];
    const float* uvmap    = (const float*)d_in[4];

    int V = in_sizes[0] / 3;
    int K = in_sizes[1] / 3;
    int T = (int)(sqrt((double)(in_sizes[4] / 3)) + 0.5);
    int S = (int)(sqrt((double)(out_size / 4)) + 0.5);
    if (K > MAXK) K = MAXK;

    setup_kernel<<<1, 1024>>>(vertices, faces, V, K);
    build_kernel<<<(K + 255) / 256, 256>>>(vertices, faces, K);

    dim3 blk(32, 8);
    dim3 grd((S + 31) / 32, (S + 7) / 8);
    render_kernel<<<grd, blk>>>(uvfaces, uv, uvmap, (float*)d_out, S, T);
}

// round 6
// speedup vs baseline: 2.4919x; 1.8309x over previous
#include <cuda_runtime.h>
#include <math.h>

// ----------------------------------------------------------------------------
// Software rasterizer matching the JAX reference.
// winner(pixel) = lexicographic argmax over covering triangles of (z, index),
// zbuf init = min vertex z. Deferred shading (one bilinear sample per pixel).
// Triangles bucket-sorted by zmax desc; per-slot term key = exact suffix max of
// zmax. Render blocks compact each chunk against their pixel tile before the
// per-pixel scan (conservative separable edge-max test, margin 1e-3).
// ----------------------------------------------------------------------------

#define MAXK  2048
#define CHUNK 256
#define NBUK  256

__device__ float4 g_tri[MAXK * 4];   // bucket-ordered triangle structs
__device__ int    g_ntri;            // number of active slots
__device__ float  g_zinit;           // min vertex z

__device__ __forceinline__ float blk_reduce(float v, bool do_min, float* s_red, int tid) {
    // warp shfl reduce + cross-warp via smem (32 entries)
    for (int o = 16; o > 0; o >>= 1) {
        float u = __shfl_xor_sync(0xffffffffu, v, o);
        v = do_min ? fminf(v, u) : fmaxf(v, u);
    }
    if ((tid & 31) == 0) s_red[tid >> 5] = v;
    __syncthreads();
    if (tid < 32) {
        float u = s_red[tid];
        for (int o = 16; o > 0; o >>= 1) {
            float w = __shfl_xor_sync(0xffffffffu, u, o);
            u = do_min ? fminf(u, w) : fmaxf(u, w);
        }
        if (tid == 0) s_red[0] = u;
    }
    __syncthreads();
    float r = s_red[0];
    __syncthreads();
    return r;
}

// ---- fused setup: zinit + zmax + bucket sort + suffix max + struct build ---
__global__ void __launch_bounds__(1024) setup_kernel(
    const float* __restrict__ vertices, const int* __restrict__ faces,
    int V, int K)
{
    __shared__ float s_zmax[MAXK];
    __shared__ float s_bufA[MAXK];
    __shared__ float s_bufB[MAXK];
    __shared__ int   s_pos[MAXK];
    __shared__ int   s_hist[NBUK];
    __shared__ int   s_cnt[NBUK];
    __shared__ float s_red[32];
    int tid = threadIdx.x;

    // 1. zinit = min vertex z
    float m = INFINITY;
    for (int v = tid; v < V; v += 1024) m = fminf(m, vertices[v * 3 + 2]);
    m = blk_reduce(m, true, s_red, tid);
    if (tid == 0) g_zinit = m;

    // 2. per-triangle zmax (-inf if culled)
    float mymax = -INFINITY, mymin = INFINITY;
    for (int t = tid; t < K; t += 1024) {
        int i0 = faces[3*t], i1 = faces[3*t+1], i2 = faces[3*t+2];
        float v0x = vertices[i0*3+0], v0y = vertices[i0*3+1], v0z = vertices[i0*3+2];
        float v1x = vertices[i1*3+0], v1y = vertices[i1*3+1], v1z = vertices[i1*3+2];
        float v2x = vertices[i2*3+0], v2y = vertices[i2*3+1], v2z = vertices[i2*3+2];
        float w = (v1x - v0x) * (v2y - v0y) - (v1y - v0y) * (v2x - v0x);
        float zm = -INFINITY;
        if (w >= 1e-9f) {
            zm = fmaxf(v0z, fmaxf(v1z, v2z));
            mymax = fmaxf(mymax, zm);
            mymin = fminf(mymin, zm);
        }
        s_zmax[t] = zm;
    }
    float zh = blk_reduce(mymax, false, s_red, tid);
    float zl = blk_reduce(mymin, true,  s_red, tid);
    float wd = fmaxf((zh - zl) / (float)NBUK, 1e-30f);

    // 3. histogram (bucket 0 = highest zmax)
    if (tid < NBUK) s_hist[tid] = 0;
    __syncthreads();
    for (int t = tid; t < K; t += 1024) {
        float zm = s_zmax[t];
        if (zm != -INFINITY) {
            int b = (int)((zh - zm) / wd);
            b = min(max(b, 0), NBUK - 1);
            atomicAdd(&s_hist[b], 1);
        }
    }
    __syncthreads();

    // 4. inclusive scan -> exclusive starts
    int cval = (tid < NBUK) ? s_hist[tid] : 0;
    if (tid < NBUK) s_cnt[tid] = cval;
    __syncthreads();
    for (int off = 1; off < NBUK; off <<= 1) {
        int v = 0;
        if (tid < NBUK && tid >= off) v = s_cnt[tid - off];
        __syncthreads();
        if (tid < NBUK) s_cnt[tid] += v;
        __syncthreads();
    }
    __shared__ int sh_n;
    if (tid == NBUK - 1) sh_n = s_cnt[tid];
    __syncthreads();
    if (tid < NBUK) s_cnt[tid] -= cval;
    __syncthreads();

    // 5. scatter slot assignment + per-slot zmax
    for (int t = tid; t < K; t += 1024) {
        float zm = s_zmax[t];
        int pos = -1;
        if (zm != -INFINITY) {
            int b = (int)((zh - zm) / wd);
            b = min(max(b, 0), NBUK - 1);
            pos = atomicAdd(&s_cnt[b], 1);
            s_bufA[pos] = zm;
        }
        s_pos[t] = pos;
    }
    int n = sh_n;
    if (tid == 0) g_ntri = n;
    for (int i2 = tid; i2 < MAXK; i2 += 1024)
        if (i2 >= n) s_bufA[i2] = -INFINITY;
    __syncthreads();

    // 6. exact suffix max over slots (ping-pong Hillis-Steele)
    float* src = s_bufA;
    float* dst = s_bufB;
    for (int off = 1; off < MAXK; off <<= 1) {
        for (int i2 = tid; i2 < MAXK; i2 += 1024) {
            float a = src[i2];
            float b2 = (i2 + off < MAXK) ? src[i2 + off] : -INFINITY;
            dst[i2] = fmaxf(a, b2);
        }
        __syncthreads();
        float* tmp = src; src = dst; dst = tmp;
    }

    // 7. build structs (vertex/face loads are L1-hot from step 2)
    // Layout per slot (4 x float4):
    //  [0] A0 B0 C0 term   (edge pAB: A*px + B*py + C; term = suffix-max zmax)
    //  [1] A1 B1 C1 z0     (edge pCB -> w1)
    //  [2] A2 B2 C2 z1     (edge pCA -> w2)
    //  [3] w   z2  idx  0
    for (int t = tid; t < K; t += 1024) {
        int pos = s_pos[t];
        if (pos < 0) continue;
        int i0 = faces[t*3+0], i1 = faces[t*3+1], i2 = faces[t*3+2];
        float v0x = vertices[i0*3+0], v0y = vertices[i0*3+1], v0z = vertices[i0*3+2];
        float v1x = vertices[i1*3+0], v1y = vertices[i1*3+1], v1z = vertices[i1*3+2];
        float v2x = vertices[i2*3+0], v2y = vertices[i2*3+1], v2z = vertices[i2*3+2];
        float w = (v1x - v0x) * (v2y - v0y) - (v1y - v0y) * (v2x - v0x);

        float a0 = v0y - v1y, b0 = v0x - v1x;
        float C0 = (float)((double)v1y * (double)b0 - (double)v1x * (double)a0);
        float a1 = v1y - v2y, b1 = v1x - v2x;
        float C1 = (float)((double)v2y * (double)b1 - (double)v2x * (double)a1);
        float a2 = v2y - v0y, b2 = v2x - v0x;
        float C2 = (float)((double)v0y * (double)b2 - (double)v0x * (double)a2);

        g_tri[pos*4+0] = make_float4(a0, -b0, C0, src[pos]);
        g_tri[pos*4+1] = make_float4(a1, -b1, C1, v0z);
        g_tri[pos*4+2] = make_float4(a2, -b2, C2, v1z);
        g_tri[pos*4+3] = make_float4(w, v2z, __int_as_float(t), 0.0f);
    }
}

// ---- main render -----------------------------------------------------------
__global__ void __launch_bounds__(256) render_kernel(
    const int* __restrict__ uvfaces, const float* __restrict__ uv,
    const float* __restrict__ uvmap, float* __restrict__ out,
    int S, int T)
{
    __shared__ float4 s_tri[CHUNK * 4];
    __shared__ int    s_list[CHUNK];
    __shared__ int    s_wcnt[8];
    __shared__ int    s_woff[8];
    __shared__ int    s_lcnt;

    int n = g_ntri;

    int j = blockIdx.x * 32 + threadIdx.x;
    int i = blockIdx.y * 8 + threadIdx.y;
    int tid = threadIdx.y * 32 + threadIdx.x;
    int warp = tid >> 5, lane = tid & 31;
    bool inrange = (j < S) && (i < S);
    int jc = min(j, S - 1), ic = min(i, S - 1);

    // pts[i][j] = (lin[j], lin[S-1-i]), lin = linspace(-1, 1, S)
    float step = 2.0f / (float)(S - 1);
    float px = fmaf((float)jc, step, -1.0f);
    float py = fmaf((float)(S - 1 - ic), step, -1.0f);

    // tile bounds in (px, py) space (fmaf is monotone in the index)
    int j0 = min(blockIdx.x * 32,      S - 1), j1 = min(blockIdx.x * 32 + 31, S - 1);
    int i0 = min(blockIdx.y * 8,       S - 1), i1 = min(blockIdx.y * 8 + 7,   S - 1);
    float xl = fmaf((float)j0, step, -1.0f), xh = fmaf((float)j1, step, -1.0f);
    float yl = fmaf((float)(S - 1 - i1), step, -1.0f);
    float yh = fmaf((float)(S - 1 - i0), step, -1.0f);

    float bestz = g_zinit;
    int   bestk = -1;
    float bw1 = 0.f, bw2 = 0.f;
    bool done = false;

    for (int base = 0; base < n; base += CHUNK) {
        int cnt = min(CHUNK, n - base);
        __syncthreads();
        for (int idx = tid; idx < cnt * 4; idx += 256)
            s_tri[idx] = g_tri[base * 4 + idx];
        __syncthreads();

        // --- cooperative tile compaction (order-preserving) ---
        bool keep = false;
        if (tid < cnt) {
            float4 a = s_tri[tid*4+0];
            float4 b = s_tri[tid*4+1];
            float4 c = s_tri[tid*4+2];
            // max of affine edge fn over tile rectangle (separable)
            float m0 = fmaxf(a.x*xl, a.x*xh) + fmaxf(a.y*yl, a.y*yh) + a.z;
            float m1 = fmaxf(b.x*xl, b.x*xh) + fmaxf(b.y*yl, b.y*yh) + b.z;
            float m2 = fmaxf(c.x*xl, c.x*xh) + fmaxf(c.y*yl, c.y*yh) + c.z;
            keep = (fminf(m0, fminf(m1, m2)) > -1e-3f);  // safety margin >> f32 slack
        }
        unsigned ball = __ballot_sync(0xffffffffu, keep);
        int pre = __popc(ball & ((1u << lane) - 1u));
        if (lane == 0) s_wcnt[warp] = __popc(ball);
        __syncthreads();
        if (tid == 0) {
            int s = 0;
            #pragma unroll
            for (int w = 0; w < 8; ++w) { s_woff[w] = s; s += s_wcnt[w]; }
            s_lcnt = s;
        }
        __syncthreads();
        if (keep) s_list[s_woff[warp] + pre] = tid;
        __syncthreads();
        int lcnt = s_lcnt;

        if (!done) {
            if (s_tri[0].w < bestz) {
                done = true;   // chunk head term can't beat bestz -> nothing later can
            } else {
                for (int m = 0; m < lcnt; ++m) {
                    int t = s_list[m];
                    float4 a = s_tri[t*4+0];
                    if (a.w < bestz) { done = true; break; }  // global suffix max
                    float e0 = fmaf(a.x, px, fmaf(a.y, py, a.z));
                    float4 b = s_tri[t*4+1];
                    float e1 = fmaf(b.x, px, fmaf(b.y, py, b.z));
                    float4 c = s_tri[t*4+2];
                    float e2 = fmaf(c.x, px, fmaf(c.y, py, c.z));
                    if (fminf(e0, fminf(e1, e2)) > 0.f) {
                        float4 d = s_tri[t*4+3];
                        float w1 = e1 / d.x;          // pCB / w (exact like ref)
                        float w2 = e2 / d.x;          // pCA / w
                        float w3 = 1.0f - w1 - w2;
                        float z = w1 * b.w + w2 * c.w + w3 * d.y;
                        int k = __float_as_int(d.z);
                        if (z > bestz || (z == bestz && k > bestk)) {
                            bestz = z; bestk = k; bw1 = w1; bw2 = w2;
                        }
                    }
                }
            }
        }
        if (__syncthreads_and((int)done)) break;
    }

    if (!inrange) return;
    int SS = S * S;
    int p = i * S + j;

    if (bestk >= 0) {
        int f0 = uvfaces[bestk*3+0], f1 = uvfaces[bestk*3+1], f2i = uvfaces[bestk*3+2];
        float u0x = uv[f0*2+0]  * 2.0f - 1.0f, u0y = uv[f0*2+1]  * 2.0f - 1.0f;
        float u1x = uv[f1*2+0]  * 2.0f - 1.0f, u1y = uv[f1*2+1]  * 2.0f - 1.0f;
        float u2x = uv[f2i*2+0] * 2.0f - 1.0f, u2y = uv[f2i*2+1] * 2.0f - 1.0f;
        float w3 = 1.0f - bw1 - bw2;
        float x = bw1 * u0x + bw2 * u1x + w3 * u2x;
        float y = bw1 * u0y + bw2 * u1y + w3 * u2y;

        float ix = (x + 1.0f) * (float)(T - 1) * 0.5f;
        float iy = (y + 1.0f) * (float)(T - 1) * 0.5f;
        float ix0f = floorf(ix), iy0f = floorf(iy);
        float wx1 = ix - ix0f, wx0 = 1.0f - wx1;
        float wy1 = iy - iy0f, wy0 = 1.0f - wy1;
        int ix0 = (int)ix0f, iy0 = (int)iy0f;
        int ix1 = ix0 + 1,   iy1 = iy0 + 1;

        float m00 = (ix0 >= 0 && ix0 <= T-1 && iy0 >= 0 && iy0 <= T-1) ? 1.f : 0.f;
        float m01 = (ix1 >= 0 && ix1 <= T-1 && iy0 >= 0 && iy0 <= T-1) ? 1.f : 0.f;
        float m10 = (ix0 >= 0 && ix0 <= T-1 && iy1 >= 0 && iy1 <= T-1) ? 1.f : 0.f;
        float m11 = (ix1 >= 0 && ix1 <= T-1 && iy1 >= 0 && iy1 <= T-1) ? 1.f : 0.f;
        int cx0 = min(max(ix0, 0), T-1), cx1 = min(max(ix1, 0), T-1);
        int cy0 = min(max(iy0, 0), T-1), cy1 = min(max(iy1, 0), T-1);
        float k00 = (wy0 * wx0) * m00, k01 = (wy0 * wx1) * m01;
        float k10 = (wy1 * wx0) * m10, k11 = (wy1 * wx1) * m11;

        #pragma unroll
        for (int ch = 0; ch < 3; ++ch) {
            const float* img = uvmap + ch * T * T;
            float v = img[cy0*T + cx0] * k00 + img[cy0*T + cx1] * k01
                    + img[cy1*T + cx0] * k10 + img[cy1*T + cx1] * k11;
            out[ch*SS + p] = v;
        }
        out[3*SS + p] = 1.0f;
    } else {
        out[0*SS + p] = 0.f; out[1*SS + p] = 0.f;
        out[2*SS + p] = 0.f; out[3*SS + p] = 0.f;
    }
}

// ---- launch ----------------------------------------------------------------
extern "C" void kernel_launch(void* const* d_in, const int* in_sizes, int n_in,
                              void* d_out, int out_size) {
    const float* vertices = (const float*)d_in[0];
    const int*   faces    = (const int*)d_in[1];
    const float* uv       = (const float*)d_in[2];
    const int*   uvfaces  = (const int*)d_in[3];
    const float* uvmap    = (const float*)d_in[4];

    int V = in_sizes[0] / 3;
    int K = in_sizes[1] / 3;
    int T = (int)(sqrt((double)(in_sizes[4] / 3)) + 0.5);
    int S = (int)(sqrt((double)(out_size / 4)) + 0.5);
    if (K > MAXK) K = MAXK;

    setup_kernel<<<1, 1024>>>(vertices, faces, V, K);

    dim3 blk(32, 8);
    dim3 grd((S + 31) / 32, (S + 7) / 8);
    render_kernel<<<grd, blk>>>(uvfaces, uv, uvmap, (float*)d_out, S, T);
}

// round 7
// speedup vs baseline: 2.6888x; 1.0790x over previous
#include <cuda_runtime.h>
#include <math.h>

// ----------------------------------------------------------------------------
// Software rasterizer matching the JAX reference.
// winner(pixel) = lexicographic argmax over covering triangles of (z, index),
// zbuf init = min vertex z. Deferred shading (one bilinear sample per pixel).
// Triangles bucket-sorted by zmax desc; per-slot term key = bucket upper edge
// (+1 bucket pad) -> non-increasing and >= all remaining zmax, so early
// termination is exact. Render blocks compact each chunk against their pixel
// tile at load time (global->reg->test->smem), scanning only survivors.
// ----------------------------------------------------------------------------

#define MAXK  2048
#define CHUNK 256
#define NBUK  256

__device__ float4 g_tri[MAXK * 4];   // bucket-ordered triangle structs
__device__ int    g_ntri;            // number of active slots
__device__ float  g_zinit;           // min vertex z

__device__ __forceinline__ float blk_reduce(float v, bool do_min, float* s_red, int tid) {
    for (int o = 16; o > 0; o >>= 1) {
        float u = __shfl_xor_sync(0xffffffffu, v, o);
        v = do_min ? fminf(v, u) : fmaxf(v, u);
    }
    if ((tid & 31) == 0) s_red[tid >> 5] = v;
    __syncthreads();
    if (tid < 32) {
        float u = s_red[tid];
        for (int o = 16; o > 0; o >>= 1) {
            float w = __shfl_xor_sync(0xffffffffu, u, o);
            u = do_min ? fminf(u, w) : fmaxf(u, w);
        }
        if (tid == 0) s_red[0] = u;
    }
    __syncthreads();
    float r = s_red[0];
    __syncthreads();
    return r;
}

// ---- fused setup: zinit + zmax + bucket sort + struct build ----------------
__global__ void __launch_bounds__(1024) setup_kernel(
    const float* __restrict__ vertices, const int* __restrict__ faces,
    int V, int K)
{
    __shared__ float s_zmax[MAXK];
    __shared__ int   s_pos[MAXK];
    __shared__ int   s_hist[NBUK];
    __shared__ int   s_cnt[NBUK];
    __shared__ float s_red[32];
    int tid = threadIdx.x;

    // 1. zinit = min vertex z
    float m = INFINITY;
    for (int v = tid; v < V; v += 1024) m = fminf(m, vertices[v * 3 + 2]);
    m = blk_reduce(m, true, s_red, tid);
    if (tid == 0) g_zinit = m;

    // 2. per-triangle zmax (-inf if culled)
    float mymax = -INFINITY, mymin = INFINITY;
    for (int t = tid; t < K; t += 1024) {
        int i0 = faces[3*t], i1 = faces[3*t+1], i2 = faces[3*t+2];
        float v0x = vertices[i0*3+0], v0y = vertices[i0*3+1], v0z = vertices[i0*3+2];
        float v1x = vertices[i1*3+0], v1y = vertices[i1*3+1], v1z = vertices[i1*3+2];
        float v2x = vertices[i2*3+0], v2y = vertices[i2*3+1], v2z = vertices[i2*3+2];
        float w = (v1x - v0x) * (v2y - v0y) - (v1y - v0y) * (v2x - v0x);
        float zm = -INFINITY;
        if (w >= 1e-9f) {
            zm = fmaxf(v0z, fmaxf(v1z, v2z));
            mymax = fmaxf(mymax, zm);
            mymin = fminf(mymin, zm);
        }
        s_zmax[t] = zm;
    }
    float zh = blk_reduce(mymax, false, s_red, tid);
    float zl = blk_reduce(mymin, true,  s_red, tid);
    float wd = fmaxf((zh - zl) / (float)NBUK, 1e-30f);

    // 3. histogram (bucket 0 = highest zmax)
    if (tid < NBUK) s_hist[tid] = 0;
    __syncthreads();
    for (int t = tid; t < K; t += 1024) {
        float zm = s_zmax[t];
        if (zm != -INFINITY) {
            int b = (int)((zh - zm) / wd);
            b = min(max(b, 0), NBUK - 1);
            atomicAdd(&s_hist[b], 1);
        }
    }
    __syncthreads();

    // 4. inclusive scan -> exclusive starts
    int cval = (tid < NBUK) ? s_hist[tid] : 0;
    if (tid < NBUK) s_cnt[tid] = cval;
    __syncthreads();
    for (int off = 1; off < NBUK; off <<= 1) {
        int v = 0;
        if (tid < NBUK && tid >= off) v = s_cnt[tid - off];
        __syncthreads();
        if (tid < NBUK) s_cnt[tid] += v;
        __syncthreads();
    }
    __shared__ int sh_n;
    if (tid == NBUK - 1) sh_n = s_cnt[tid];
    __syncthreads();
    if (tid < NBUK) s_cnt[tid] -= cval;
    __syncthreads();

    // 5. scatter slot assignment
    for (int t = tid; t < K; t += 1024) {
        float zm = s_zmax[t];
        int pos = -1;
        if (zm != -INFINITY) {
            int b = (int)((zh - zm) / wd);
            b = min(max(b, 0), NBUK - 1);
            pos = atomicAdd(&s_cnt[b], 1);
        }
        s_pos[t] = pos;
    }
    if (tid == 0) g_ntri = sh_n;
    __syncthreads();

    // 6. build structs. term key = bucket upper edge + one-bucket pad:
    //    term(b) = zh - (b-1)*wd  >= zmax of everything in buckets >= b
    //    (margin ~wd >> f32 rounding), and non-increasing across slots.
    // Layout per slot (4 x float4):
    //  [0] A0 B0 C0 term   (edge pAB: A*px + B*py + C)
    //  [1] A1 B1 C1 z0     (edge pCB -> w1)
    //  [2] A2 B2 C2 z1     (edge pCA -> w2)
    //  [3] w   z2  idx  0
    for (int t = tid; t < K; t += 1024) {
        int pos = s_pos[t];
        if (pos < 0) continue;
        float zm = s_zmax[t];
        int b = (int)((zh - zm) / wd);
        b = min(max(b, 0), NBUK - 1);
        float term = zh - (float)(b - 1) * wd;

        int i0 = faces[t*3+0], i1 = faces[t*3+1], i2 = faces[t*3+2];
        float v0x = vertices[i0*3+0], v0y = vertices[i0*3+1], v0z = vertices[i0*3+2];
        float v1x = vertices[i1*3+0], v1y = vertices[i1*3+1], v1z = vertices[i1*3+2];
        float v2x = vertices[i2*3+0], v2y = vertices[i2*3+1], v2z = vertices[i2*3+2];
        float w = (v1x - v0x) * (v2y - v0y) - (v1y - v0y) * (v2x - v0x);

        float a0 = v0y - v1y, b0 = v0x - v1x;
        float C0 = (float)((double)v1y * (double)b0 - (double)v1x * (double)a0);
        float a1 = v1y - v2y, b1 = v1x - v2x;
        float C1 = (float)((double)v2y * (double)b1 - (double)v2x * (double)a1);
        float a2 = v2y - v0y, b2 = v2x - v0x;
        float C2 = (float)((double)v0y * (double)b2 - (double)v0x * (double)a2);

        g_tri[pos*4+0] = make_float4(a0, -b0, C0, term);
        g_tri[pos*4+1] = make_float4(a1, -b1, C1, v0z);
        g_tri[pos*4+2] = make_float4(a2, -b2, C2, v1z);
        g_tri[pos*4+3] = make_float4(w, v2z, __int_as_float(t), 0.0f);
    }
}

// ---- main render -----------------------------------------------------------
__global__ void __launch_bounds__(256) render_kernel(
    const int* __restrict__ uvfaces, const float* __restrict__ uv,
    const float* __restrict__ uvmap, float* __restrict__ out,
    int S, int T)
{
    __shared__ float4 s_ktri[CHUNK * 4];   // compacted survivors (dense)
    __shared__ int    s_wcnt[8];
    __shared__ int    s_woff[8];
    __shared__ int    s_lcnt;
    __shared__ float  s_head;              // chunk-head term key

    int n = g_ntri;

    int j = blockIdx.x * 32 + threadIdx.x;
    int i = blockIdx.y * 8 + threadIdx.y;
    int tid = threadIdx.y * 32 + threadIdx.x;
    int warp = tid >> 5, lane = tid & 31;
    bool inrange = (j < S) && (i < S);
    int jc = min(j, S - 1), ic = min(i, S - 1);

    // pts[i][j] = (lin[j], lin[S-1-i]), lin = linspace(-1, 1, S)
    float step = 2.0f / (float)(S - 1);
    float px = fmaf((float)jc, step, -1.0f);
    float py = fmaf((float)(S - 1 - ic), step, -1.0f);

    // tile bounds in (px, py) space
    int j0 = min(blockIdx.x * 32,      S - 1), j1 = min(blockIdx.x * 32 + 31, S - 1);
    int i0 = min(blockIdx.y * 8,       S - 1), i1 = min(blockIdx.y * 8 + 7,   S - 1);
    float xl = fmaf((float)j0, step, -1.0f), xh = fmaf((float)j1, step, -1.0f);
    float yl = fmaf((float)(S - 1 - i1), step, -1.0f);
    float yh = fmaf((float)(S - 1 - i0), step, -1.0f);

    float bestz = g_zinit;
    int   bestk = -1;
    float bw1 = 0.f, bw2 = 0.f;
    bool done = false;

    for (int base = 0; base < n; base += CHUNK) {
        int cnt = min(CHUNK, n - base);
        __syncthreads();   // protect s_ktri reuse across iterations

        // --- compact-on-load: global -> registers -> tile test -> smem ---
        bool keep = false;
        float4 r0, r1, r2;
        if (tid < cnt) {
            const float4* gp = &g_tri[(base + tid) * 4];
            r0 = gp[0]; r1 = gp[1]; r2 = gp[2];
            if (tid == 0) s_head = r0.w;
            // max of affine edge fn over tile rectangle (separable)
            float m0 = fmaxf(r0.x*xl, r0.x*xh) + fmaxf(r0.y*yl, r0.y*yh) + r0.z;
            float m1 = fmaxf(r1.x*xl, r1.x*xh) + fmaxf(r1.y*yl, r1.y*yh) + r1.z;
            float m2 = fmaxf(r2.x*xl, r2.x*xh) + fmaxf(r2.y*yl, r2.y*yh) + r2.z;
            keep = (fminf(m0, fminf(m1, m2)) > -1e-3f);  // margin >> f32 slack
        }
        unsigned ball = __ballot_sync(0xffffffffu, keep);
        int pre = __popc(ball & ((1u << lane) - 1u));
        if (lane == 0) s_wcnt[warp] = __popc(ball);
        __syncthreads();
        if (tid == 0) {
            int s = 0;
            #pragma unroll
            for (int w = 0; w < 8; ++w) { s_woff[w] = s; s += s_wcnt[w]; }
            s_lcnt = s;
        }
        __syncthreads();
        if (keep) {
            float4 r3 = g_tri[(base + tid) * 4 + 3];
            int pos = s_woff[warp] + pre;
            s_ktri[pos*4+0] = r0;
            s_ktri[pos*4+1] = r1;
            s_ktri[pos*4+2] = r2;
            s_ktri[pos*4+3] = r3;
        }
        __syncthreads();
        int lcnt = s_lcnt;

        if (!done) {
            if (s_head < bestz) {
                done = true;   // chunk-head term can't beat bestz -> nothing later can
            } else {
                for (int mI = 0; mI < lcnt; ++mI) {
                    float4 a = s_ktri[mI*4+0];
                    if (a.w < bestz) { done = true; break; }  // term non-increasing
                    float e0 = fmaf(a.x, px, fmaf(a.y, py, a.z));
                    float4 b = s_ktri[mI*4+1];
                    float e1 = fmaf(b.x, px, fmaf(b.y, py, b.z));
                    float4 c = s_ktri[mI*4+2];
                    float e2 = fmaf(c.x, px, fmaf(c.y, py, c.z));
                    if (fminf(e0, fminf(e1, e2)) > 0.f) {
                        float4 d = s_ktri[mI*4+3];
                        float w1 = e1 / d.x;          // pCB / w (exact like ref)
                        float w2 = e2 / d.x;          // pCA / w
                        float w3 = 1.0f - w1 - w2;
                        float z = w1 * b.w + w2 * c.w + w3 * d.y;
                        int k = __float_as_int(d.z);
                        if (z > bestz || (z == bestz && k > bestk)) {
                            bestz = z; bestk = k; bw1 = w1; bw2 = w2;
                        }
                    }
                }
            }
        }
        if (__syncthreads_and((int)done)) break;
    }

    if (!inrange) return;
    int SS = S * S;
    int p = i * S + j;

    if (bestk >= 0) {
        int f0 = uvfaces[bestk*3+0], f1 = uvfaces[bestk*3+1], f2i = uvfaces[bestk*3+2];
        float u0x = uv[f0*2+0]  * 2.0f - 1.0f, u0y = uv[f0*2+1]  * 2.0f - 1.0f;
        float u1x = uv[f1*2+0]  * 2.0f - 1.0f, u1y = uv[f1*2+1]  * 2.0f - 1.0f;
        float u2x = uv[f2i*2+0] * 2.0f - 1.0f, u2y = uv[f2i*2+1] * 2.0f - 1.0f;
        float w3 = 1.0f - bw1 - bw2;
        float x = bw1 * u0x + bw2 * u1x + w3 * u2x;
        float y = bw1 * u0y + bw2 * u1y + w3 * u2y;

        float ix = (x + 1.0f) * (float)(T - 1) * 0.5f;
        float iy = (y + 1.0f) * (float)(T - 1) * 0.5f;
        float ix0f = floorf(ix), iy0f = floorf(iy);
        float wx1 = ix - ix0f, wx0 = 1.0f - wx1;
        float wy1 = iy - iy0f, wy0 = 1.0f - wy1;
        int ix0 = (int)ix0f, iy0 = (int)iy0f;
        int ix1 = ix0 + 1,   iy1 = iy0 + 1;

        float m00 = (ix0 >= 0 && ix0 <= T-1 && iy0 >= 0 && iy0 <= T-1) ? 1.f : 0.f;
        float m01 = (ix1 >= 0 && ix1 <= T-1 && iy0 >= 0 && iy0 <= T-1) ? 1.f : 0.f;
        float m10 = (ix0 >= 0 && ix0 <= T-1 && iy1 >= 0 && iy1 <= T-1) ? 1.f : 0.f;
        float m11 = (ix1 >= 0 && ix1 <= T-1 && iy1 >= 0 && iy1 <= T-1) ? 1.f : 0.f;
        int cx0 = min(max(ix0, 0), T-1), cx1 = min(max(ix1, 0), T-1);
        int cy0 = min(max(iy0, 0), T-1), cy1 = min(max(iy1, 0), T-1);
        float k00 = (wy0 * wx0) * m00, k01 = (wy0 * wx1) * m01;
        float k10 = (wy1 * wx0) * m10, k11 = (wy1 * wx1) * m11;

        #pragma unroll
        for (int ch = 0; ch < 3; ++ch) {
            const float* img = uvmap + ch * T * T;
            float v = img[cy0*T + cx0] * k00 + img[cy0*T + cx1] * k01
                    + img[cy1*T + cx0] * k10 + img[cy1*T + cx1] * k11;
            out[ch*SS + p] = v;
        }
        out[3*SS + p] = 1.0f;
    } else {
        out[0*SS + p] = 0.f; out[1*SS + p] = 0.f;
        out[2*SS + p] = 0.f; out[3*SS + p] = 0.f;
    }
}

// ---- launch ----------------------------------------------------------------
extern "C" void kernel_launch(void* const* d_in, const int* in_sizes, int n_in,
                              void* d_out, int out_size) {
    const float* vertices = (const float*)d_in[0];
    const int*   faces    = (const int*)d_in[1];
    const float* uv       = (const float*)d_in[2];
    const int*   uvfaces  = (const int*)d_in[3];
    const float* uvmap    = (const float*)d_in[4];

    int V = in_sizes[0] / 3;
    int K = in_sizes[1] / 3;
    int T = (int)(sqrt((double)(in_sizes[4] / 3)) + 0.5);
    int S = (int)(sqrt((double)(out_size / 4)) + 0.5);
    if (K > MAXK) K = MAXK;

    setup_kernel<<<1, 1024>>>(vertices, faces, V, K);

    dim3 blk(32, 8);
    dim3 grd((S + 31) / 32, (S + 7) / 8);
    render_kernel<<<grd, blk>>>(uvfaces, uv, uvmap, (float*)d_out, S, T);
}